// round 1
// baseline (speedup 1.0000x reference)
#include <cuda_runtime.h>

// Polynomial attention (degree 2), B=2 H=16 S=2048 D=64, fp32.
// out[b,h,s,:] = sum_t (q_s . k_t)^2 * v_t / max(sum_t (q_s . k_t)^2, 1e-4)
//
// Single-pass flash-style: per query tile, loop over KV tiles, accumulate
// numerator and denominator, divide at the end. No max-subtraction needed.

#define S_LEN 2048
#define D_DIM 64
#define BM 128          // query rows per CTA
#define BN 64           // key rows per tile
#define NTHREADS 256
#define EPS_CLAMP 1e-4f

// smem leading dims (floats)
#define LDQ 64          // Qs [BM][64]  (broadcast reads -> no pad needed)
#define LDK 65          // Ks [BN][65]  (odd pad -> 2-way max conflict on scalar reads)
#define LDV 64          // Vs [BN][64]  (float4 reads, 2-way max)
#define LDP 68          // Ps [BM][68]  (float4 writes aligned, broadcast reads)

#define SMEM_FLOATS (BM * LDQ + BN * LDK + BN * LDV + BM * LDP)
#define SMEM_BYTES (SMEM_FLOATS * 4)

__global__ void __launch_bounds__(NTHREADS, 2)
poly_attn_kernel(const float* __restrict__ q,
                 const float* __restrict__ k,
                 const float* __restrict__ v,
                 float* __restrict__ out) {
    extern __shared__ float smem[];
    float* Qs = smem;                       // [BM][LDQ]
    float* Ks = Qs + BM * LDQ;              // [BN][LDK]
    float* Vs = Ks + BN * LDK;              // [BN][LDV]
    float* Ps = Vs + BN * LDV;              // [BM][LDP]

    const int bh = blockIdx.y;              // 0..31 (B*H)
    const int mt = blockIdx.x;              // 0..15 (query tile)
    const size_t base = (size_t)bh * S_LEN * D_DIM;
    const float* Qg = q + base + (size_t)mt * BM * D_DIM;
    const float* Kg = k + base;
    const float* Vg = v + base;
    float* Og = out + base + (size_t)mt * BM * D_DIM;

    const int tid = threadIdx.x;
    const int mg = tid >> 4;                // 0..15 -> query row group
    const int ng = tid & 15;                // 0..15 -> col group
    const int m0 = mg * 8;                  // 8 query rows per thread
    const int n0 = ng * 4;                  // 4 cols per thread

    // ---- load Q tile [BM][64] (float4 copy, natural layout) ----
    {
        const float4* src = (const float4*)Qg;
        float4* dst = (float4*)Qs;
#pragma unroll
        for (int r = 0; r < (BM * D_DIM / 4) / NTHREADS; r++) {
            int i4 = tid + r * NTHREADS;
            dst[i4] = src[i4];
        }
    }

    float o_acc[8][4];
    float dsum[8];
#pragma unroll
    for (int i = 0; i < 8; i++) {
        dsum[i] = 0.f;
#pragma unroll
        for (int j = 0; j < 4; j++) o_acc[i][j] = 0.f;
    }

    for (int nt = 0; nt < S_LEN / BN; nt++) {
        __syncthreads();  // prior phase-2 done before overwriting Ks/Vs

        // ---- load K tile -> Ks[n][d] (ld=65, scalar stores), V tile -> Vs (float4) ----
        {
            const float4* ksrc = (const float4*)(Kg + (size_t)nt * BN * D_DIM);
            const float4* vsrc = (const float4*)(Vg + (size_t)nt * BN * D_DIM);
            float4* vdst = (float4*)Vs;
#pragma unroll
            for (int r = 0; r < (BN * D_DIM / 4) / NTHREADS; r++) {
                int i4 = tid + r * NTHREADS;
                int n = i4 >> 4;              // 16 float4 per row
                int d0 = (i4 & 15) * 4;
                float4 kv = ksrc[i4];
                float* kp = Ks + n * LDK + d0;
                kp[0] = kv.x; kp[1] = kv.y; kp[2] = kv.z; kp[3] = kv.w;
                vdst[i4] = vsrc[i4];          // LDV==64 => same linear layout
            }
        }
        __syncthreads();

        // ---- phase 1: S = Q K^T  (thread: rows m0..m0+7 x cols n0..n0+3) ----
        float acc[8][4];
#pragma unroll
        for (int i = 0; i < 8; i++)
#pragma unroll
            for (int j = 0; j < 4; j++) acc[i][j] = 0.f;

#pragma unroll 4
        for (int kk = 0; kk < D_DIM; kk++) {
            float a[8], b[4];
#pragma unroll
            for (int i = 0; i < 8; i++) a[i] = Qs[(m0 + i) * LDQ + kk];
#pragma unroll
            for (int j = 0; j < 4; j++) b[j] = Ks[(n0 + j) * LDK + kk];
#pragma unroll
            for (int i = 0; i < 8; i++)
#pragma unroll
                for (int j = 0; j < 4; j++) acc[i][j] = fmaf(a[i], b[j], acc[i][j]);
        }

        // ---- square, accumulate denom partials, write P tile ----
#pragma unroll
        for (int i = 0; i < 8; i++) {
            float p0 = acc[i][0] * acc[i][0];
            float p1 = acc[i][1] * acc[i][1];
            float p2 = acc[i][2] * acc[i][2];
            float p3 = acc[i][3] * acc[i][3];
            dsum[i] += (p0 + p1) + (p2 + p3);
            float4 pv = make_float4(p0, p1, p2, p3);
            *(float4*)(Ps + (m0 + i) * LDP + n0) = pv;
        }
        __syncthreads();

        // ---- phase 2: O += P @ V  (thread: rows m0..m0+7 x out cols n0..n0+3) ----
#pragma unroll 4
        for (int kk = 0; kk < BN; kk++) {
            float4 bv = *(const float4*)(Vs + kk * LDV + n0);
#pragma unroll
            for (int i = 0; i < 8; i++) {
                float a = Ps[(m0 + i) * LDP + kk];
                o_acc[i][0] = fmaf(a, bv.x, o_acc[i][0]);
                o_acc[i][1] = fmaf(a, bv.y, o_acc[i][1]);
                o_acc[i][2] = fmaf(a, bv.z, o_acc[i][2]);
                o_acc[i][3] = fmaf(a, bv.w, o_acc[i][3]);
            }
        }
    }

    // ---- reduce denom across the 16 threads (ng) sharing each row group ----
    // threads with equal mg occupy one contiguous 16-lane half-warp; xor<16 stays in-group
#pragma unroll
    for (int i = 0; i < 8; i++) {
        float s = dsum[i];
        s += __shfl_xor_sync(0xffffffffu, s, 1);
        s += __shfl_xor_sync(0xffffffffu, s, 2);
        s += __shfl_xor_sync(0xffffffffu, s, 4);
        s += __shfl_xor_sync(0xffffffffu, s, 8);
        dsum[i] = s;
    }

    // ---- normalize and store ----
#pragma unroll
    for (int i = 0; i < 8; i++) {
        float inv = 1.0f / fmaxf(dsum[i], EPS_CLAMP);
        float4 o;
        o.x = o_acc[i][0] * inv;
        o.y = o_acc[i][1] * inv;
        o.z = o_acc[i][2] * inv;
        o.w = o_acc[i][3] * inv;
        *(float4*)(Og + (m0 + i) * D_DIM + n0) = o;
    }
}

extern "C" void kernel_launch(void* const* d_in, const int* in_sizes, int n_in,
                              void* d_out, int out_size) {
    (void)in_sizes; (void)n_in; (void)out_size;
    const float* q = (const float*)d_in[0];
    const float* k = (const float*)d_in[1];
    const float* v = (const float*)d_in[2];
    float* out = (float*)d_out;

    cudaFuncSetAttribute(poly_attn_kernel,
                         cudaFuncAttributeMaxDynamicSharedMemorySize, SMEM_BYTES);

    dim3 grid(S_LEN / BM, 32);  // 16 query tiles x (B*H)=32
    poly_attn_kernel<<<grid, NTHREADS, SMEM_BYTES>>>(q, k, v, out);
}

// round 2
// speedup vs baseline: 1.6356x; 1.6356x over previous
#include <cuda_runtime.h>

// Polynomial attention (degree 2), B=2 H=16 S=2048 D=64, fp32.
// out[b,h,s,:] = sum_t (q_s . k_t)^2 * v_t / max(sum_t (q_s . k_t)^2, 1e-4)
//
// Single-pass flash-style: per query tile, loop over KV tiles, accumulate
// numerator and denominator, divide at the end. No max-subtraction needed.

#define S_LEN 2048
#define D_DIM 64
#define BM 128          // query rows per CTA
#define BN 64           // key rows per tile
#define NTHREADS 256
#define EPS_CLAMP 1e-4f

// smem leading dims (floats)
#define LDQ 64          // Qs [BM][64]  (broadcast reads -> no pad needed)
#define LDK 65          // Ks [BN][65]  (odd pad -> 2-way max conflict on scalar reads)
#define LDV 64          // Vs [BN][64]  (float4 reads, 2-way max)
#define LDP 68          // Ps [BM][68]  (float4 writes aligned, broadcast reads)

#define SMEM_FLOATS (BM * LDQ + BN * LDK + BN * LDV + BM * LDP)
#define SMEM_BYTES (SMEM_FLOATS * 4)

__global__ void __launch_bounds__(NTHREADS, 2)
poly_attn_kernel(const float* __restrict__ q,
                 const float* __restrict__ k,
                 const float* __restrict__ v,
                 float* __restrict__ out) {
    extern __shared__ float smem[];
    float* Qs = smem;                       // [BM][LDQ]
    float* Ks = Qs + BM * LDQ;              // [BN][LDK]
    float* Vs = Ks + BN * LDK;              // [BN][LDV]
    float* Ps = Vs + BN * LDV;              // [BM][LDP]

    const int bh = blockIdx.y;              // 0..31 (B*H)
    const int mt = blockIdx.x;              // 0..15 (query tile)
    const size_t base = (size_t)bh * S_LEN * D_DIM;
    const float* Qg = q + base + (size_t)mt * BM * D_DIM;
    const float* Kg = k + base;
    const float* Vg = v + base;
    float* Og = out + base + (size_t)mt * BM * D_DIM;

    const int tid = threadIdx.x;
    const int mg = tid >> 4;                // 0..15 -> query row group
    const int ng = tid & 15;                // 0..15 -> col group
    const int m0 = mg * 8;                  // 8 query rows per thread
    const int n0 = ng * 4;                  // 4 cols per thread

    // ---- load Q tile [BM][64] (float4 copy, natural layout) ----
    {
        const float4* src = (const float4*)Qg;
        float4* dst = (float4*)Qs;
#pragma unroll
        for (int r = 0; r < (BM * D_DIM / 4) / NTHREADS; r++) {
            int i4 = tid + r * NTHREADS;
            dst[i4] = src[i4];
        }
    }

    float o_acc[8][4];
    float dsum[8];
#pragma unroll
    for (int i = 0; i < 8; i++) {
        dsum[i] = 0.f;
#pragma unroll
        for (int j = 0; j < 4; j++) o_acc[i][j] = 0.f;
    }

    for (int nt = 0; nt < S_LEN / BN; nt++) {
        __syncthreads();  // prior phase-2 done before overwriting Ks/Vs

        // ---- load K tile -> Ks[n][d] (ld=65, scalar stores), V tile -> Vs (float4) ----
        {
            const float4* ksrc = (const float4*)(Kg + (size_t)nt * BN * D_DIM);
            const float4* vsrc = (const float4*)(Vg + (size_t)nt * BN * D_DIM);
            float4* vdst = (float4*)Vs;
#pragma unroll
            for (int r = 0; r < (BN * D_DIM / 4) / NTHREADS; r++) {
                int i4 = tid + r * NTHREADS;
                int n = i4 >> 4;              // 16 float4 per row
                int d0 = (i4 & 15) * 4;
                float4 kv = ksrc[i4];
                float* kp = Ks + n * LDK + d0;
                kp[0] = kv.x; kp[1] = kv.y; kp[2] = kv.z; kp[3] = kv.w;
                vdst[i4] = vsrc[i4];          // LDV==64 => same linear layout
            }
        }
        __syncthreads();

        // ---- phase 1: S = Q K^T  (thread: rows m0..m0+7 x cols n0..n0+3) ----
        float acc[8][4];
#pragma unroll
        for (int i = 0; i < 8; i++)
#pragma unroll
            for (int j = 0; j < 4; j++) acc[i][j] = 0.f;

#pragma unroll 4
        for (int kk = 0; kk < D_DIM; kk++) {
            float a[8], b[4];
#pragma unroll
            for (int i = 0; i < 8; i++) a[i] = Qs[(m0 + i) * LDQ + kk];
#pragma unroll
            for (int j = 0; j < 4; j++) b[j] = Ks[(n0 + j) * LDK + kk];
#pragma unroll
            for (int i = 0; i < 8; i++)
#pragma unroll
                for (int j = 0; j < 4; j++) acc[i][j] = fmaf(a[i], b[j], acc[i][j]);
        }

        // ---- square, accumulate denom partials, write P tile ----
#pragma unroll
        for (int i = 0; i < 8; i++) {
            float p0 = acc[i][0] * acc[i][0];
            float p1 = acc[i][1] * acc[i][1];
            float p2 = acc[i][2] * acc[i][2];
            float p3 = acc[i][3] * acc[i][3];
            dsum[i] += (p0 + p1) + (p2 + p3);
            float4 pv = make_float4(p0, p1, p2, p3);
            *(float4*)(Ps + (m0 + i) * LDP + n0) = pv;
        }
        __syncthreads();

        // ---- phase 2: O += P @ V  (thread: rows m0..m0+7 x out cols n0..n0+3) ----
#pragma unroll 4
        for (int kk = 0; kk < BN; kk++) {
            float4 bv = *(const float4*)(Vs + kk * LDV + n0);
#pragma unroll
            for (int i = 0; i < 8; i++) {
                float a = Ps[(m0 + i) * LDP + kk];
                o_acc[i][0] = fmaf(a, bv.x, o_acc[i][0]);
                o_acc[i][1] = fmaf(a, bv.y, o_acc[i][1]);
                o_acc[i][2] = fmaf(a, bv.z, o_acc[i][2]);
                o_acc[i][3] = fmaf(a, bv.w, o_acc[i][3]);
            }
        }
    }

    // ---- reduce denom across the 16 threads (ng) sharing each row group ----
    // threads with equal mg occupy one contiguous 16-lane half-warp; xor<16 stays in-group
#pragma unroll
    for (int i = 0; i < 8; i++) {
        float s = dsum[i];
        s += __shfl_xor_sync(0xffffffffu, s, 1);
        s += __shfl_xor_sync(0xffffffffu, s, 2);
        s += __shfl_xor_sync(0xffffffffu, s, 4);
        s += __shfl_xor_sync(0xffffffffu, s, 8);
        dsum[i] = s;
    }

    // ---- normalize and store ----
#pragma unroll
    for (int i = 0; i < 8; i++) {
        float inv = 1.0f / fmaxf(dsum[i], EPS_CLAMP);
        float4 o;
        o.x = o_acc[i][0] * inv;
        o.y = o_acc[i][1] * inv;
        o.z = o_acc[i][2] * inv;
        o.w = o_acc[i][3] * inv;
        *(float4*)(Og + (m0 + i) * D_DIM + n0) = o;
    }
}

extern "C" void kernel_launch(void* const* d_in, const int* in_sizes, int n_in,
                              void* d_out, int out_size) {
    (void)in_sizes; (void)n_in; (void)out_size;
    const float* q = (const float*)d_in[0];
    const float* k = (const float*)d_in[1];
    const float* v = (const float*)d_in[2];
    float* out = (float*)d_out;

    cudaFuncSetAttribute(poly_attn_kernel,
                         cudaFuncAttributeMaxDynamicSharedMemorySize, SMEM_BYTES);

    dim3 grid(S_LEN / BM, 32);  // 16 query tiles x (B*H)=32
    poly_attn_kernel<<<grid, NTHREADS, SMEM_BYTES>>>(q, k, v, out);
}

// round 4
// speedup vs baseline: 2.9578x; 1.8084x over previous
#include <cuda_runtime.h>
#include <cstdint>

// Polynomial attention deg-2, B=2 H=16 S=2048 D=64 fp32.
// mma.sync m16n8k8 tf32 path (arch-portable PTX; tcgen05 unavailable: harness
// PTX targets sm_103 without the 'a' feature suffix).
//
// S = Qh*Kh^T + Qh*Kl^T + Ql*Kh^T   (3xTF32 exact-split, err ~1e-6)
// P = rna_tf32(S^2) ; denom accumulated in registers from P
// O += P * V_tf32   (register accumulators across all key tiles)

#define SLEN 2048
#define DDIM 64
#define BM 128
#define BT 64
#define NITER (SLEN / BT)
#define EPS_CLAMP 1e-4f

// smem leading dims (floats). Chosen for conflict-free mma fragment LDS:
//  A-operand (addr = row*ld + k, row=t/4, k=t%4): ld%32==4 -> bank 4r+k distinct
//  B-operand K (addr = n*ld + k,  n=t/4, k=t%4): ld%32==4 -> distinct
//  B-operand V (addr = k*ld + n,  k=t%4, n=t/4): ld%32==8 -> bank 8k+n distinct
#define LDQ 68
#define LDK 68
#define LDV 72
#define LDP 68

// smem float offsets
#define OF_QH 0
#define OF_QL (OF_QH + BM * LDQ)
#define OF_KH (OF_QL + BM * LDQ)
#define OF_KL (OF_KH + BT * LDK)
#define OF_V  (OF_KL + BT * LDK)
#define OF_P  (OF_V + BT * LDV)
#define OF_DS (OF_P + BM * LDP)
#define SMEM_FLOATS (OF_DS + BM)
#define SMEM_BYTES (SMEM_FLOATS * 4)

__device__ __forceinline__ float tf32_hi(float x) {
    return __uint_as_float(__float_as_uint(x) & 0xFFFFE000u);
}
__device__ __forceinline__ float tf32_rna(float x) {
    uint32_t u;
    asm("cvt.rna.tf32.f32 %0, %1;" : "=r"(u) : "f"(x));
    return __uint_as_float(u);
}

__device__ __forceinline__ void mma8(float* d, const uint32_t* a, const uint32_t* b) {
    asm("mma.sync.aligned.m16n8k8.row.col.f32.tf32.tf32.f32 "
        "{%0,%1,%2,%3}, {%4,%5,%6,%7}, {%8,%9}, {%0,%1,%2,%3};"
        : "+f"(d[0]), "+f"(d[1]), "+f"(d[2]), "+f"(d[3])
        : "r"(a[0]), "r"(a[1]), "r"(a[2]), "r"(a[3]), "r"(b[0]), "r"(b[1]));
}

__global__ void __launch_bounds__(256, 1)
poly_attn_mma(const float* __restrict__ q, const float* __restrict__ k,
              const float* __restrict__ v, float* __restrict__ out) {
    extern __shared__ float sm[];
    const uint32_t* smu = (const uint32_t*)sm;
    const int tid = threadIdx.x;
    const int wid = tid >> 5, lane = tid & 31;
    const int wm = wid & 1, wn = wid >> 1;   // warp tile: rows 64*wm, cols 16*wn
    const int tq = lane >> 2, tc = lane & 3;
    const int bh = blockIdx.y, mt = blockIdx.x;

    if (tid < BM) sm[OF_DS + tid] = 0.f;

    // ---- load Q tile [128][64], split hi/lo (exact-mask + rna residual) ----
    {
        const float4* qg = (const float4*)(q + ((size_t)bh * SLEN + (size_t)mt * BM) * DDIM);
#pragma unroll
        for (int r = 0; r < 8; r++) {
            int i4 = tid + r * 256;
            int row = i4 >> 4, c4 = (i4 & 15) * 4;
            float4 x = qg[i4];
            float4 h, l;
            h.x = tf32_hi(x.x); l.x = tf32_rna(x.x - h.x);
            h.y = tf32_hi(x.y); l.y = tf32_rna(x.y - h.y);
            h.z = tf32_hi(x.z); l.z = tf32_rna(x.z - h.z);
            h.w = tf32_hi(x.w); l.w = tf32_rna(x.w - h.w);
            *(float4*)(sm + OF_QH + row * LDQ + c4) = h;
            *(float4*)(sm + OF_QL + row * LDQ + c4) = l;
        }
    }

    const float4* kg = (const float4*)(k + (size_t)bh * SLEN * DDIM);
    const float4* vg = (const float4*)(v + (size_t)bh * SLEN * DDIM);

    // prefetch key-tile 0 into registers
    float4 kf[4], vf[4];
#pragma unroll
    for (int r = 0; r < 4; r++) {
        kf[r] = kg[tid + r * 256];
        vf[r] = vg[tid + r * 256];
    }

    float oacc[4][2][4];
    float dsl[4], dsh[4];
#pragma unroll
    for (int rt = 0; rt < 4; rt++) {
        dsl[rt] = 0.f; dsh[rt] = 0.f;
#pragma unroll
        for (int ct = 0; ct < 2; ct++)
#pragma unroll
            for (int j = 0; j < 4; j++) oacc[rt][ct][j] = 0.f;
    }

    // fragment base offsets (floats)
    int qoff[4], poffA[4], koff[2], voff[2];
#pragma unroll
    for (int rt = 0; rt < 4; rt++) {
        qoff[rt]  = (64 * wm + 16 * rt + tq) * LDQ + tc;
        poffA[rt] = (64 * wm + 16 * rt + tq) * LDP + tc;
    }
#pragma unroll
    for (int ct = 0; ct < 2; ct++) {
        koff[ct] = (16 * wn + 8 * ct + tq) * LDK + tc;
        voff[ct] = tc * LDV + 16 * wn + 8 * ct + tq;
    }

    for (int nt = 0; nt < NITER; nt++) {
        __syncthreads();  // prev GEMM2 done reading V/P before overwrite

        // ---- store prefetched K (split) and V (rna) tiles ----
#pragma unroll
        for (int r = 0; r < 4; r++) {
            int i4 = tid + r * 256;
            int row = i4 >> 4, c4 = (i4 & 15) * 4;
            float4 x = kf[r];
            float4 h, l;
            h.x = tf32_hi(x.x); l.x = tf32_rna(x.x - h.x);
            h.y = tf32_hi(x.y); l.y = tf32_rna(x.y - h.y);
            h.z = tf32_hi(x.z); l.z = tf32_rna(x.z - h.z);
            h.w = tf32_hi(x.w); l.w = tf32_rna(x.w - h.w);
            *(float4*)(sm + OF_KH + row * LDK + c4) = h;
            *(float4*)(sm + OF_KL + row * LDK + c4) = l;
            float4 y = vf[r];
            y.x = tf32_rna(y.x); y.y = tf32_rna(y.y);
            y.z = tf32_rna(y.z); y.w = tf32_rna(y.w);
            *(float4*)(sm + OF_V + row * LDV + c4) = y;
        }
        __syncthreads();

        // prefetch next tile (overlaps with GEMM work below)
        if (nt + 1 < NITER) {
#pragma unroll
            for (int r = 0; r < 4; r++) {
                kf[r] = kg[(nt + 1) * 1024 + tid + r * 256];
                vf[r] = vg[(nt + 1) * 1024 + tid + r * 256];
            }
        }

        // ---- GEMM1: S[128x64] = Qh Kh^T + Qh Kl^T + Ql Kh^T ----
        float sacc[4][2][4];
#pragma unroll
        for (int rt = 0; rt < 4; rt++)
#pragma unroll
            for (int ct = 0; ct < 2; ct++)
#pragma unroll
                for (int j = 0; j < 4; j++) sacc[rt][ct][j] = 0.f;

        for (int ks = 0; ks < 8; ks++) {
            int ko = ks * 8;
            uint32_t ah[4][4], al[4][4];
#pragma unroll
            for (int rt = 0; rt < 4; rt++) {
                int o = qoff[rt] + ko;
                ah[rt][0] = smu[OF_QH + o];
                ah[rt][1] = smu[OF_QH + o + 8 * LDQ];
                ah[rt][2] = smu[OF_QH + o + 4];
                ah[rt][3] = smu[OF_QH + o + 8 * LDQ + 4];
                al[rt][0] = smu[OF_QL + o];
                al[rt][1] = smu[OF_QL + o + 8 * LDQ];
                al[rt][2] = smu[OF_QL + o + 4];
                al[rt][3] = smu[OF_QL + o + 8 * LDQ + 4];
            }
            uint32_t bhf[2][2], blf[2][2];
#pragma unroll
            for (int ct = 0; ct < 2; ct++) {
                int o = koff[ct] + ko;
                bhf[ct][0] = smu[OF_KH + o];
                bhf[ct][1] = smu[OF_KH + o + 4];
                blf[ct][0] = smu[OF_KL + o];
                blf[ct][1] = smu[OF_KL + o + 4];
            }
#pragma unroll
            for (int rt = 0; rt < 4; rt++)
#pragma unroll
                for (int ct = 0; ct < 2; ct++) {
                    mma8(sacc[rt][ct], ah[rt], bhf[ct]);
                    mma8(sacc[rt][ct], ah[rt], blf[ct]);
                    mma8(sacc[rt][ct], al[rt], bhf[ct]);
                }
        }

        // ---- epilogue: P = rna_tf32(S^2), denom partials, P -> smem ----
#pragma unroll
        for (int rt = 0; rt < 4; rt++) {
#pragma unroll
            for (int ct = 0; ct < 2; ct++) {
                float p0 = tf32_rna(sacc[rt][ct][0] * sacc[rt][ct][0]);
                float p1 = tf32_rna(sacc[rt][ct][1] * sacc[rt][ct][1]);
                float p2 = tf32_rna(sacc[rt][ct][2] * sacc[rt][ct][2]);
                float p3 = tf32_rna(sacc[rt][ct][3] * sacc[rt][ct][3]);
                dsl[rt] += p0 + p1;
                dsh[rt] += p2 + p3;
                int wa = (64 * wm + 16 * rt + tq) * LDP + 16 * wn + 8 * ct + 2 * tc;
                *(float2*)(sm + OF_P + wa) = make_float2(p0, p1);
                *(float2*)(sm + OF_P + wa + 8 * LDP) = make_float2(p2, p3);
            }
        }
        __syncthreads();

        // ---- GEMM2: O[128x64] += P[128x64(keys)] * V[64(keys)x64] ----
        for (int ks = 0; ks < 8; ks++) {
            int ko = ks * 8;
            uint32_t pa[4][4];
#pragma unroll
            for (int rt = 0; rt < 4; rt++) {
                int o = poffA[rt] + ko;
                pa[rt][0] = smu[OF_P + o];
                pa[rt][1] = smu[OF_P + o + 8 * LDP];
                pa[rt][2] = smu[OF_P + o + 4];
                pa[rt][3] = smu[OF_P + o + 8 * LDP + 4];
            }
            uint32_t vb[2][2];
#pragma unroll
            for (int ct = 0; ct < 2; ct++) {
                int o = voff[ct] + ko * LDV;
                vb[ct][0] = smu[OF_V + o];
                vb[ct][1] = smu[OF_V + o + 4 * LDV];
            }
#pragma unroll
            for (int rt = 0; rt < 4; rt++)
#pragma unroll
                for (int ct = 0; ct < 2; ct++)
                    mma8(oacc[rt][ct], pa[rt], vb[ct]);
        }
    }

    // ---- denominator: reduce over tc lanes, then across the 4 wn warps ----
#pragma unroll
    for (int rt = 0; rt < 4; rt++) {
        dsl[rt] += __shfl_xor_sync(0xffffffffu, dsl[rt], 1);
        dsl[rt] += __shfl_xor_sync(0xffffffffu, dsl[rt], 2);
        dsh[rt] += __shfl_xor_sync(0xffffffffu, dsh[rt], 1);
        dsh[rt] += __shfl_xor_sync(0xffffffffu, dsh[rt], 2);
    }
    if (tc == 0) {
#pragma unroll
        for (int rt = 0; rt < 4; rt++) {
            atomicAdd(&sm[OF_DS + 64 * wm + 16 * rt + tq], dsl[rt]);
            atomicAdd(&sm[OF_DS + 64 * wm + 16 * rt + tq + 8], dsh[rt]);
        }
    }
    __syncthreads();

    // ---- normalize and store ----
    float* og = out + ((size_t)bh * SLEN + (size_t)mt * BM) * DDIM;
#pragma unroll
    for (int rt = 0; rt < 4; rt++) {
        int rlo = 64 * wm + 16 * rt + tq;
        float il = 1.f / fmaxf(sm[OF_DS + rlo], EPS_CLAMP);
        float ih = 1.f / fmaxf(sm[OF_DS + rlo + 8], EPS_CLAMP);
#pragma unroll
        for (int ct = 0; ct < 2; ct++) {
            int dcol = 16 * wn + 8 * ct + 2 * tc;
            *(float2*)(og + (size_t)rlo * DDIM + dcol) =
                make_float2(oacc[rt][ct][0] * il, oacc[rt][ct][1] * il);
            *(float2*)(og + (size_t)(rlo + 8) * DDIM + dcol) =
                make_float2(oacc[rt][ct][2] * ih, oacc[rt][ct][3] * ih);
        }
    }
}

extern "C" void kernel_launch(void* const* d_in, const int* in_sizes, int n_in,
                              void* d_out, int out_size) {
    (void)in_sizes; (void)n_in; (void)out_size;
    const float* q = (const float*)d_in[0];
    const float* k = (const float*)d_in[1];
    const float* v = (const float*)d_in[2];
    float* out = (float*)d_out;

    cudaFuncSetAttribute(poly_attn_mma,
                         cudaFuncAttributeMaxDynamicSharedMemorySize, SMEM_BYTES);
    poly_attn_mma<<<dim3(SLEN / BM, 32), 256, SMEM_BYTES>>>(q, k, v, out);
}

// round 5
// speedup vs baseline: 3.2327x; 1.0929x over previous
#include <cuda_runtime.h>
#include <cstdint>

// Polynomial attention deg-2, B=2 H=16 S=2048 D=64 fp32.
// mma.sync m16n8k8 tf32; warp-owns-rows; P stays in registers (shuffle
// re-layout acc->A-frag); K/V double-buffered; one __syncthreads per iter.

#define SLEN 2048
#define DDIM 64
#define BM 128
#define BT 64
#define NITER (SLEN / BT)
#define EPS_CLAMP 1e-4f

#define LDQ 68   // (4*tq+tc)%32 distinct -> conflict-free A frags
#define LDK 68
#define LDV 72   // (8*tc+tq)%32 distinct -> conflict-free B frags

// smem float offsets
#define OF_QH 0
#define OF_QL (OF_QH + BM * LDQ)
#define OF_KH (OF_QL + BM * LDQ)          // [2][BT][LDK]
#define OF_KL (OF_KH + 2 * BT * LDK)      // [2][BT][LDK]
#define OF_V  (OF_KL + 2 * BT * LDK)      // [2][BT][LDV]
#define SMEM_FLOATS (OF_V + 2 * BT * LDV)
#define SMEM_BYTES (SMEM_FLOATS * 4)

__device__ __forceinline__ float tf32_hi(float x) {
    return __uint_as_float(__float_as_uint(x) & 0xFFFFE000u);
}
__device__ __forceinline__ float tf32_rna(float x) {
    uint32_t u;
    asm("cvt.rna.tf32.f32 %0, %1;" : "=r"(u) : "f"(x));
    return __uint_as_float(u);
}
__device__ __forceinline__ void mma8(float* d, const uint32_t* a, const uint32_t* b) {
    asm("mma.sync.aligned.m16n8k8.row.col.f32.tf32.tf32.f32 "
        "{%0,%1,%2,%3}, {%4,%5,%6,%7}, {%8,%9}, {%0,%1,%2,%3};"
        : "+f"(d[0]), "+f"(d[1]), "+f"(d[2]), "+f"(d[3])
        : "r"(a[0]), "r"(a[1]), "r"(a[2]), "r"(a[3]), "r"(b[0]), "r"(b[1]));
}

__global__ void __launch_bounds__(256, 1)
poly_attn_mma(const float* __restrict__ q, const float* __restrict__ k,
              const float* __restrict__ v, float* __restrict__ out) {
    extern __shared__ float sm[];
    const uint32_t* smu = (const uint32_t*)sm;
    const int tid = threadIdx.x;
    const int wid = tid >> 5, lane = tid & 31;
    const int tq = lane >> 2, tc = lane & 3;
    const int bh = blockIdx.y, mt = blockIdx.x;
    const int m0 = wid * 16;                 // this warp's 16 query rows

    // ---- load Q tile [128][64], split hi/lo ----
    {
        const float4* qg = (const float4*)(q + ((size_t)bh * SLEN + (size_t)mt * BM) * DDIM);
#pragma unroll
        for (int r = 0; r < 8; r++) {
            int i4 = tid + r * 256;
            int row = i4 >> 4, c4 = (i4 & 15) * 4;
            float4 x = qg[i4];
            float4 h, l;
            h.x = tf32_hi(x.x); l.x = tf32_rna(x.x - h.x);
            h.y = tf32_hi(x.y); l.y = tf32_rna(x.y - h.y);
            h.z = tf32_hi(x.z); l.z = tf32_rna(x.z - h.z);
            h.w = tf32_hi(x.w); l.w = tf32_rna(x.w - h.w);
            *(float4*)(sm + OF_QH + row * LDQ + c4) = h;
            *(float4*)(sm + OF_QL + row * LDQ + c4) = l;
        }
    }

    const float4* kg = (const float4*)(k + (size_t)bh * SLEN * DDIM);
    const float4* vg = (const float4*)(v + (size_t)bh * SLEN * DDIM);

    float4 kf[4], vf[4];
    // store K-split/V tile from regs into smem buffer `buf`
    auto store_tile = [&](int buf) {
        float* KH = sm + OF_KH + buf * BT * LDK;
        float* KL = sm + OF_KL + buf * BT * LDK;
        float* VB = sm + OF_V + buf * BT * LDV;
#pragma unroll
        for (int r = 0; r < 4; r++) {
            int i4 = tid + r * 256;
            int row = i4 >> 4, c4 = (i4 & 15) * 4;
            float4 x = kf[r];
            float4 h, l;
            h.x = tf32_hi(x.x); l.x = tf32_rna(x.x - h.x);
            h.y = tf32_hi(x.y); l.y = tf32_rna(x.y - h.y);
            h.z = tf32_hi(x.z); l.z = tf32_rna(x.z - h.z);
            h.w = tf32_hi(x.w); l.w = tf32_rna(x.w - h.w);
            *(float4*)(KH + row * LDK + c4) = h;
            *(float4*)(KL + row * LDK + c4) = l;
            float4 y = vf[r];
            y.x = tf32_rna(y.x); y.y = tf32_rna(y.y);
            y.z = tf32_rna(y.z); y.w = tf32_rna(y.w);
            *(float4*)(VB + row * LDV + c4) = y;
        }
    };

    // prologue: tile0 -> buf0, prefetch tile1
#pragma unroll
    for (int r = 0; r < 4; r++) { kf[r] = kg[tid + r * 256]; vf[r] = vg[tid + r * 256]; }
    store_tile(0);
#pragma unroll
    for (int r = 0; r < 4; r++) { kf[r] = kg[1024 + tid + r * 256]; vf[r] = vg[1024 + tid + r * 256]; }
    __syncthreads();

    float oacc[8][4];
    float dl = 0.f, dh = 0.f;
#pragma unroll
    for (int ct = 0; ct < 8; ct++)
#pragma unroll
        for (int j = 0; j < 4; j++) oacc[ct][j] = 0.f;

    const int qoff = (m0 + tq) * LDQ + tc;
    const int slo = 4 * tq + (tc >> 1);      // shuffle sources for acc->A relayout
    const int shi = slo + 2;
    const bool odd = (tc & 1);

    for (int nt = 0; nt < NITER; nt++) {
        const int buf = nt & 1;
        if (nt + 1 < NITER) store_tile(1 - buf);        // overlaps with GEMM1
        if (nt + 2 < NITER) {
#pragma unroll
            for (int r = 0; r < 4; r++) {
                kf[r] = kg[(nt + 2) * 1024 + tid + r * 256];
                vf[r] = vg[(nt + 2) * 1024 + tid + r * 256];
            }
        }

        const int KHo = OF_KH + buf * BT * LDK;
        const int KLo = OF_KL + buf * BT * LDK;
        const int Vo  = OF_V  + buf * BT * LDV;

        // ---- GEMM1: S[16x64] = Qh Kh^T + Qh Kl^T + Ql Kh^T ----
        float sacc[8][4];
#pragma unroll
        for (int ct = 0; ct < 8; ct++)
#pragma unroll
            for (int j = 0; j < 4; j++) sacc[ct][j] = 0.f;

#pragma unroll
        for (int ks = 0; ks < 8; ks++) {
            const int ko = ks * 8;
            uint32_t ah[4], al[4];
            {
                int o = qoff + ko;
                ah[0] = smu[OF_QH + o];
                ah[1] = smu[OF_QH + o + 8 * LDQ];
                ah[2] = smu[OF_QH + o + 4];
                ah[3] = smu[OF_QH + o + 8 * LDQ + 4];
                al[0] = smu[OF_QL + o];
                al[1] = smu[OF_QL + o + 8 * LDQ];
                al[2] = smu[OF_QL + o + 4];
                al[3] = smu[OF_QL + o + 8 * LDQ + 4];
            }
#pragma unroll
            for (int ct = 0; ct < 8; ct++) {
                const int o = (8 * ct + tq) * LDK + ko + tc;
                uint32_t bhf[2], blf[2];
                bhf[0] = smu[KHo + o]; bhf[1] = smu[KHo + o + 4];
                blf[0] = smu[KLo + o]; blf[1] = smu[KLo + o + 4];
                mma8(sacc[ct], ah, bhf);
                mma8(sacc[ct], ah, blf);
                mma8(sacc[ct], al, bhf);
            }
        }

        // ---- epilogue in registers: P = rna(S^2); denom partials ----
#pragma unroll
        for (int ct = 0; ct < 8; ct++) {
            sacc[ct][0] = tf32_rna(sacc[ct][0] * sacc[ct][0]);
            sacc[ct][1] = tf32_rna(sacc[ct][1] * sacc[ct][1]);
            sacc[ct][2] = tf32_rna(sacc[ct][2] * sacc[ct][2]);
            sacc[ct][3] = tf32_rna(sacc[ct][3] * sacc[ct][3]);
            dl += sacc[ct][0] + sacc[ct][1];
            dh += sacc[ct][2] + sacc[ct][3];
        }

        // ---- GEMM2: O[16x64] += P[16x64] * V[64x64] (A via shuffles) ----
#pragma unroll
        for (int ks = 0; ks < 8; ks++) {
            uint32_t a[4];
            {
                float p0l = __shfl_sync(0xffffffffu, sacc[ks][0], slo);
                float p1l = __shfl_sync(0xffffffffu, sacc[ks][1], slo);
                float p2l = __shfl_sync(0xffffffffu, sacc[ks][2], slo);
                float p3l = __shfl_sync(0xffffffffu, sacc[ks][3], slo);
                float p0h = __shfl_sync(0xffffffffu, sacc[ks][0], shi);
                float p1h = __shfl_sync(0xffffffffu, sacc[ks][1], shi);
                float p2h = __shfl_sync(0xffffffffu, sacc[ks][2], shi);
                float p3h = __shfl_sync(0xffffffffu, sacc[ks][3], shi);
                a[0] = __float_as_uint(odd ? p1l : p0l);   // (row tq,   key tc)
                a[1] = __float_as_uint(odd ? p3l : p2l);   // (row tq+8, key tc)
                a[2] = __float_as_uint(odd ? p1h : p0h);   // (row tq,   key tc+4)
                a[3] = __float_as_uint(odd ? p3h : p2h);   // (row tq+8, key tc+4)
            }
            const int vk = Vo + (8 * ks + tc) * LDV + tq;
#pragma unroll
            for (int ct = 0; ct < 8; ct++) {
                uint32_t vb[2];
                vb[0] = smu[vk + 8 * ct];
                vb[1] = smu[vk + 4 * LDV + 8 * ct];
                mma8(oacc[ct], a, vb);
            }
        }
        __syncthreads();
    }

    // ---- denominator: reduce over tc lanes (cols) ----
    dl += __shfl_xor_sync(0xffffffffu, dl, 1);
    dl += __shfl_xor_sync(0xffffffffu, dl, 2);
    dh += __shfl_xor_sync(0xffffffffu, dh, 1);
    dh += __shfl_xor_sync(0xffffffffu, dh, 2);
    const float il = 1.f / fmaxf(dl, EPS_CLAMP);
    const float ih = 1.f / fmaxf(dh, EPS_CLAMP);

    // ---- normalize and store ----
    float* og = out + ((size_t)bh * SLEN + (size_t)mt * BM + m0) * DDIM;
#pragma unroll
    for (int ct = 0; ct < 8; ct++) {
        int dcol = 8 * ct + 2 * tc;
        *(float2*)(og + (size_t)tq * DDIM + dcol) =
            make_float2(oacc[ct][0] * il, oacc[ct][1] * il);
        *(float2*)(og + (size_t)(tq + 8) * DDIM + dcol) =
            make_float2(oacc[ct][2] * ih, oacc[ct][3] * ih);
    }
}

extern "C" void kernel_launch(void* const* d_in, const int* in_sizes, int n_in,
                              void* d_out, int out_size) {
    (void)in_sizes; (void)n_in; (void)out_size;
    const float* q = (const float*)d_in[0];
    const float* k = (const float*)d_in[1];
    const float* v = (const float*)d_in[2];
    float* out = (float*)d_out;

    cudaFuncSetAttribute(poly_attn_mma,
                         cudaFuncAttributeMaxDynamicSharedMemorySize, SMEM_BYTES);
    poly_attn_mma<<<dim3(SLEN / BM, 32), 256, SMEM_BYTES>>>(q, k, v, out);
}

// round 6
// speedup vs baseline: 4.4415x; 1.3739x over previous
#include <cuda_runtime.h>
#include <cuda_bf16.h>
#include <cstdint>

// Polynomial attention deg-2, B=2 H=16 S=2048 D=64 fp32.
// GEMM1: bf16 2-term split (qh+ql)(kh+kl), drop ql*kl -> 3x mma.m16n8k16.bf16
// P = rna_tf32(S^2) in regs; GEMM2: tf32 m16n8k8 P*V (A via shuffles).
// K/V double-buffered, one __syncthreads per iter.

#define SLEN 2048
#define DDIM 64
#define BM 128
#define BT 64
#define NITER (SLEN / BT)
#define EPS_CLAMP 1e-4f

// u32 leading dims: 36 -> bank = 4*tq+tc, conflict-free fragment LDS
#define LDQ2 36
#define LDK2 36
#define LDV 72

// smem offsets in 4-byte units
#define OF_QH 0
#define OF_QL (OF_QH + BM * LDQ2)            // 4608
#define OF_KH (OF_QL + BM * LDQ2)            // [2][64][36]
#define OF_KL (OF_KH + 2 * BT * LDK2)
#define OF_V  (OF_KL + 2 * BT * LDK2)        // [2][64][72] f32
#define SMEM_U32 (OF_V + 2 * BT * LDV)
#define SMEM_BYTES (SMEM_U32 * 4)

__device__ __forceinline__ float tf32_rna(float x) {
    uint32_t u;
    asm("cvt.rna.tf32.f32 %0, %1;" : "=r"(u) : "f"(x));
    return __uint_as_float(u);
}
// pack two f32 -> bf16x2 (hi goes to upper 16 bits)
__device__ __forceinline__ uint32_t packbf(float hi, float lo) {
    uint32_t u;
    asm("cvt.rn.bf16x2.f32 %0, %1, %2;" : "=r"(u) : "f"(hi), "f"(lo));
    return u;
}
__device__ __forceinline__ float bfrt(float x) {      // bf16 round-trip
    return __bfloat162float(__float2bfloat16(x));
}
__device__ __forceinline__ void mma16(float* d, const uint32_t* a, const uint32_t* b) {
    asm("mma.sync.aligned.m16n8k16.row.col.f32.bf16.bf16.f32 "
        "{%0,%1,%2,%3}, {%4,%5,%6,%7}, {%8,%9}, {%0,%1,%2,%3};"
        : "+f"(d[0]), "+f"(d[1]), "+f"(d[2]), "+f"(d[3])
        : "r"(a[0]), "r"(a[1]), "r"(a[2]), "r"(a[3]), "r"(b[0]), "r"(b[1]));
}
__device__ __forceinline__ void mma8(float* d, const uint32_t* a, const uint32_t* b) {
    asm("mma.sync.aligned.m16n8k8.row.col.f32.tf32.tf32.f32 "
        "{%0,%1,%2,%3}, {%4,%5,%6,%7}, {%8,%9}, {%0,%1,%2,%3};"
        : "+f"(d[0]), "+f"(d[1]), "+f"(d[2]), "+f"(d[3])
        : "r"(a[0]), "r"(a[1]), "r"(a[2]), "r"(a[3]), "r"(b[0]), "r"(b[1]));
}

__global__ void __launch_bounds__(256, 1)
poly_attn_mma(const float* __restrict__ q, const float* __restrict__ k,
              const float* __restrict__ v, float* __restrict__ out) {
    extern __shared__ uint32_t sm[];
    float* smf = (float*)sm;
    const int tid = threadIdx.x;
    const int wid = tid >> 5, lane = tid & 31;
    const int tq = lane >> 2, tc = lane & 3;
    const int bh = blockIdx.y, mt = blockIdx.x;
    const int m0 = wid * 16;

    // ---- Q tile [128][64] -> bf16 hi/lo pairs in smem ----
    {
        const float4* qg = (const float4*)(q + ((size_t)bh * SLEN + (size_t)mt * BM) * DDIM);
#pragma unroll
        for (int r = 0; r < 8; r++) {
            int i4 = tid + r * 256;
            int row = i4 >> 4, pr = (i4 & 15) * 2;
            float4 x = qg[i4];
            float h0 = bfrt(x.x), h1 = bfrt(x.y), h2 = bfrt(x.z), h3 = bfrt(x.w);
            uint2 hp = make_uint2(packbf(h1, h0), packbf(h3, h2));
            uint2 lp = make_uint2(packbf(x.y - h1, x.x - h0),
                                  packbf(x.w - h3, x.z - h2));
            *(uint2*)(sm + OF_QH + row * LDQ2 + pr) = hp;
            *(uint2*)(sm + OF_QL + row * LDQ2 + pr) = lp;
        }
    }

    const float4* kg = (const float4*)(k + (size_t)bh * SLEN * DDIM);
    const float4* vg = (const float4*)(v + (size_t)bh * SLEN * DDIM);

    float4 kf[4], vf[4];
    auto store_tile = [&](int buf) {
        uint32_t* KH = sm + OF_KH + buf * BT * LDK2;
        uint32_t* KL = sm + OF_KL + buf * BT * LDK2;
        float* VB = smf + OF_V + buf * BT * LDV;
#pragma unroll
        for (int r = 0; r < 4; r++) {
            int i4 = tid + r * 256;
            int row = i4 >> 4, pr = (i4 & 15) * 2, c4 = (i4 & 15) * 4;
            float4 x = kf[r];
            float h0 = bfrt(x.x), h1 = bfrt(x.y), h2 = bfrt(x.z), h3 = bfrt(x.w);
            *(uint2*)(KH + row * LDK2 + pr) = make_uint2(packbf(h1, h0), packbf(h3, h2));
            *(uint2*)(KL + row * LDK2 + pr) =
                make_uint2(packbf(x.y - h1, x.x - h0), packbf(x.w - h3, x.z - h2));
            float4 y = vf[r];
            y.x = tf32_rna(y.x); y.y = tf32_rna(y.y);
            y.z = tf32_rna(y.z); y.w = tf32_rna(y.w);
            *(float4*)(VB + row * LDV + c4) = y;
        }
    };

    // prologue: tile0 -> buf0, prefetch tile1
#pragma unroll
    for (int r = 0; r < 4; r++) { kf[r] = kg[tid + r * 256]; vf[r] = vg[tid + r * 256]; }
    store_tile(0);
#pragma unroll
    for (int r = 0; r < 4; r++) { kf[r] = kg[1024 + tid + r * 256]; vf[r] = vg[1024 + tid + r * 256]; }
    __syncthreads();

    float oacc[8][4];
    float dl = 0.f, dh = 0.f;
#pragma unroll
    for (int ct = 0; ct < 8; ct++)
#pragma unroll
        for (int j = 0; j < 4; j++) oacc[ct][j] = 0.f;

    const int qoffh = OF_QH + (m0 + tq) * LDQ2 + tc;
    const int qoffl = OF_QL + (m0 + tq) * LDQ2 + tc;
    const int slo = 4 * tq + (tc >> 1);
    const int shi = slo + 2;
    const bool odd = (tc & 1);

    for (int nt = 0; nt < NITER; nt++) {
        const int buf = nt & 1;
        if (nt + 1 < NITER) store_tile(1 - buf);
        if (nt + 2 < NITER) {
#pragma unroll
            for (int r = 0; r < 4; r++) {
                kf[r] = kg[(nt + 2) * 1024 + tid + r * 256];
                vf[r] = vg[(nt + 2) * 1024 + tid + r * 256];
            }
        }

        const int KHo = OF_KH + buf * BT * LDK2;
        const int KLo = OF_KL + buf * BT * LDK2;
        const int Vo  = OF_V  + buf * BT * LDV;

        // ---- GEMM1: S[16x64] = (qh+ql)(kh+kl)^T, drop ql*kl ----
        float sacc[8][4];
#pragma unroll
        for (int ct = 0; ct < 8; ct++)
#pragma unroll
            for (int j = 0; j < 4; j++) sacc[ct][j] = 0.f;

#pragma unroll
        for (int ks = 0; ks < 4; ks++) {      // k16 steps over D=64
            const int ko = ks * 8;            // u32-pair offset
            uint32_t ah[4], al[4];
            ah[0] = sm[qoffh + ko];
            ah[1] = sm[qoffh + ko + 8 * LDQ2];
            ah[2] = sm[qoffh + ko + 4];
            ah[3] = sm[qoffh + ko + 8 * LDQ2 + 4];
            al[0] = sm[qoffl + ko];
            al[1] = sm[qoffl + ko + 8 * LDQ2];
            al[2] = sm[qoffl + ko + 4];
            al[3] = sm[qoffl + ko + 8 * LDQ2 + 4];
#pragma unroll
            for (int ct = 0; ct < 8; ct++) {
                const int o = (8 * ct + tq) * LDK2 + ko + tc;
                uint32_t bh2[2], bl2[2];
                bh2[0] = sm[KHo + o]; bh2[1] = sm[KHo + o + 4];
                bl2[0] = sm[KLo + o]; bl2[1] = sm[KLo + o + 4];
                mma16(sacc[ct], ah, bh2);
                mma16(sacc[ct], ah, bl2);
                mma16(sacc[ct], al, bh2);
            }
        }

        // ---- epilogue: P = rna_tf32(S^2); denom partials ----
#pragma unroll
        for (int ct = 0; ct < 8; ct++) {
            sacc[ct][0] = tf32_rna(sacc[ct][0] * sacc[ct][0]);
            sacc[ct][1] = tf32_rna(sacc[ct][1] * sacc[ct][1]);
            sacc[ct][2] = tf32_rna(sacc[ct][2] * sacc[ct][2]);
            sacc[ct][3] = tf32_rna(sacc[ct][3] * sacc[ct][3]);
            dl += sacc[ct][0] + sacc[ct][1];
            dh += sacc[ct][2] + sacc[ct][3];
        }

        // ---- GEMM2 (tf32): O[16x64] += P[16x64] * V[64x64] ----
#pragma unroll
        for (int ks = 0; ks < 8; ks++) {
            uint32_t a[4];
            {
                float p0l = __shfl_sync(0xffffffffu, sacc[ks][0], slo);
                float p1l = __shfl_sync(0xffffffffu, sacc[ks][1], slo);
                float p2l = __shfl_sync(0xffffffffu, sacc[ks][2], slo);
                float p3l = __shfl_sync(0xffffffffu, sacc[ks][3], slo);
                float p0h = __shfl_sync(0xffffffffu, sacc[ks][0], shi);
                float p1h = __shfl_sync(0xffffffffu, sacc[ks][1], shi);
                float p2h = __shfl_sync(0xffffffffu, sacc[ks][2], shi);
                float p3h = __shfl_sync(0xffffffffu, sacc[ks][3], shi);
                a[0] = __float_as_uint(odd ? p1l : p0l);
                a[1] = __float_as_uint(odd ? p3l : p2l);
                a[2] = __float_as_uint(odd ? p1h : p0h);
                a[3] = __float_as_uint(odd ? p3h : p2h);
            }
            const int vk = Vo + (8 * ks + tc) * LDV + tq;
#pragma unroll
            for (int ct = 0; ct < 8; ct++) {
                uint32_t vb[2];
                vb[0] = sm[vk + 8 * ct];
                vb[1] = sm[vk + 4 * LDV + 8 * ct];
                mma8(oacc[ct], a, vb);
            }
        }
        __syncthreads();
    }

    // ---- denominator reduce over tc lanes ----
    dl += __shfl_xor_sync(0xffffffffu, dl, 1);
    dl += __shfl_xor_sync(0xffffffffu, dl, 2);
    dh += __shfl_xor_sync(0xffffffffu, dh, 1);
    dh += __shfl_xor_sync(0xffffffffu, dh, 2);
    const float il = 1.f / fmaxf(dl, EPS_CLAMP);
    const float ih = 1.f / fmaxf(dh, EPS_CLAMP);

    // ---- normalize and store ----
    float* og = out + ((size_t)bh * SLEN + (size_t)mt * BM + m0) * DDIM;
#pragma unroll
    for (int ct = 0; ct < 8; ct++) {
        int dcol = 8 * ct + 2 * tc;
        *(float2*)(og + (size_t)tq * DDIM + dcol) =
            make_float2(oacc[ct][0] * il, oacc[ct][1] * il);
        *(float2*)(og + (size_t)(tq + 8) * DDIM + dcol) =
            make_float2(oacc[ct][2] * ih, oacc[ct][3] * ih);
    }
}

extern "C" void kernel_launch(void* const* d_in, const int* in_sizes, int n_in,
                              void* d_out, int out_size) {
    (void)in_sizes; (void)n_in; (void)out_size;
    const float* q = (const float*)d_in[0];
    const float* k = (const float*)d_in[1];
    const float* v = (const float*)d_in[2];
    float* out = (float*)d_out;

    cudaFuncSetAttribute(poly_attn_mma,
                         cudaFuncAttributeMaxDynamicSharedMemorySize, SMEM_BYTES);
    poly_attn_mma<<<dim3(SLEN / BM, 32), 256, SMEM_BYTES>>>(q, k, v, out);
}

// round 7
// speedup vs baseline: 5.4710x; 1.2318x over previous
#include <cuda_runtime.h>
#include <cuda_bf16.h>
#include <cstdint>

// Polynomial attention deg-2, B=2 H=16 S=2048 D=64 fp32.
// GEMM1: bf16 2-term split, mma.m16n8k16. GEMM2: tf32 m16n8k8 (A via shuffles).
// BM=256: each warp owns 32 rows (two 16-row tiles) -> K/V fragment reuse 2x.

#define SLEN 2048
#define DDIM 64
#define BM 256
#define BT 64
#define NITER (SLEN / BT)
#define EPS_CLAMP 1e-4f

#define LDQ2 36   // u32 ld: bank = 4*tq+tc, conflict-free
#define LDK2 36
#define LDV 72    // f32 ld: bank = 8*tc+tq, conflict-free

// smem offsets (4-byte units)
#define OF_QH 0
#define OF_QL (OF_QH + BM * LDQ2)
#define OF_KH (OF_QL + BM * LDQ2)          // [2][64][36]
#define OF_KL (OF_KH + 2 * BT * LDK2)
#define OF_V  (OF_KL + 2 * BT * LDK2)      // [2][64][72] f32
#define SMEM_U32 (OF_V + 2 * BT * LDV)
#define SMEM_BYTES (SMEM_U32 * 4)

__device__ __forceinline__ float tf32_rna(float x) {
    uint32_t u;
    asm("cvt.rna.tf32.f32 %0, %1;" : "=r"(u) : "f"(x));
    return __uint_as_float(u);
}
__device__ __forceinline__ uint32_t packbf(float hi, float lo) {
    uint32_t u;
    asm("cvt.rn.bf16x2.f32 %0, %1, %2;" : "=r"(u) : "f"(hi), "f"(lo));
    return u;
}
__device__ __forceinline__ float bfrt(float x) {
    return __bfloat162float(__float2bfloat16(x));
}
__device__ __forceinline__ void mma16(float* d, const uint32_t* a, const uint32_t* b) {
    asm("mma.sync.aligned.m16n8k16.row.col.f32.bf16.bf16.f32 "
        "{%0,%1,%2,%3}, {%4,%5,%6,%7}, {%8,%9}, {%0,%1,%2,%3};"
        : "+f"(d[0]), "+f"(d[1]), "+f"(d[2]), "+f"(d[3])
        : "r"(a[0]), "r"(a[1]), "r"(a[2]), "r"(a[3]), "r"(b[0]), "r"(b[1]));
}
__device__ __forceinline__ void mma8(float* d, const uint32_t* a, const uint32_t* b) {
    asm("mma.sync.aligned.m16n8k8.row.col.f32.tf32.tf32.f32 "
        "{%0,%1,%2,%3}, {%4,%5,%6,%7}, {%8,%9}, {%0,%1,%2,%3};"
        : "+f"(d[0]), "+f"(d[1]), "+f"(d[2]), "+f"(d[3])
        : "r"(a[0]), "r"(a[1]), "r"(a[2]), "r"(a[3]), "r"(b[0]), "r"(b[1]));
}

__global__ void __launch_bounds__(256, 1)
poly_attn_mma(const float* __restrict__ q, const float* __restrict__ k,
              const float* __restrict__ v, float* __restrict__ out) {
    extern __shared__ uint32_t sm[];
    float* smf = (float*)sm;
    const int tid = threadIdx.x;
    const int wid = tid >> 5, lane = tid & 31;
    const int tq = lane >> 2, tc = lane & 3;
    const int bh = blockIdx.y, mt = blockIdx.x;
    const int m0 = wid * 32;                  // warp owns rows m0..m0+31

    // ---- Q tile [256][64] -> bf16 hi/lo pairs ----
    {
        const float4* qg = (const float4*)(q + ((size_t)bh * SLEN + (size_t)mt * BM) * DDIM);
#pragma unroll
        for (int r = 0; r < 16; r++) {
            int i4 = tid + r * 256;
            int row = i4 >> 4, pr = (i4 & 15) * 2;
            float4 x = qg[i4];
            float h0 = bfrt(x.x), h1 = bfrt(x.y), h2 = bfrt(x.z), h3 = bfrt(x.w);
            *(uint2*)(sm + OF_QH + row * LDQ2 + pr) =
                make_uint2(packbf(h1, h0), packbf(h3, h2));
            *(uint2*)(sm + OF_QL + row * LDQ2 + pr) =
                make_uint2(packbf(x.y - h1, x.x - h0), packbf(x.w - h3, x.z - h2));
        }
    }

    const float4* kg = (const float4*)(k + (size_t)bh * SLEN * DDIM);
    const float4* vg = (const float4*)(v + (size_t)bh * SLEN * DDIM);

    float4 kf[4], vf[4];
    auto store_tile = [&](int buf) {
        uint32_t* KH = sm + OF_KH + buf * BT * LDK2;
        uint32_t* KL = sm + OF_KL + buf * BT * LDK2;
        float* VB = smf + OF_V + buf * BT * LDV;
#pragma unroll
        for (int r = 0; r < 4; r++) {
            int i4 = tid + r * 256;
            int row = i4 >> 4, pr = (i4 & 15) * 2, c4 = (i4 & 15) * 4;
            float4 x = kf[r];
            float h0 = bfrt(x.x), h1 = bfrt(x.y), h2 = bfrt(x.z), h3 = bfrt(x.w);
            *(uint2*)(KH + row * LDK2 + pr) = make_uint2(packbf(h1, h0), packbf(h3, h2));
            *(uint2*)(KL + row * LDK2 + pr) =
                make_uint2(packbf(x.y - h1, x.x - h0), packbf(x.w - h3, x.z - h2));
            float4 y = vf[r];
            y.x = tf32_rna(y.x); y.y = tf32_rna(y.y);
            y.z = tf32_rna(y.z); y.w = tf32_rna(y.w);
            *(float4*)(VB + row * LDV + c4) = y;
        }
    };

#pragma unroll
    for (int r = 0; r < 4; r++) { kf[r] = kg[tid + r * 256]; vf[r] = vg[tid + r * 256]; }
    store_tile(0);
#pragma unroll
    for (int r = 0; r < 4; r++) { kf[r] = kg[1024 + tid + r * 256]; vf[r] = vg[1024 + tid + r * 256]; }
    __syncthreads();

    float oacc[2][8][4];
    float dl[2] = {0.f, 0.f}, dh[2] = {0.f, 0.f};
#pragma unroll
    for (int t = 0; t < 2; t++)
#pragma unroll
        for (int ct = 0; ct < 8; ct++)
#pragma unroll
            for (int j = 0; j < 4; j++) oacc[t][ct][j] = 0.f;

    const int qoffh0 = OF_QH + (m0 + tq) * LDQ2 + tc;
    const int qoffl0 = OF_QL + (m0 + tq) * LDQ2 + tc;
    const int slo = 4 * tq + (tc >> 1);
    const int shi = slo + 2;
    const bool odd = (tc & 1);

    for (int nt = 0; nt < NITER; nt++) {
        const int buf = nt & 1;
        if (nt + 1 < NITER) store_tile(1 - buf);
        if (nt + 2 < NITER) {
#pragma unroll
            for (int r = 0; r < 4; r++) {
                kf[r] = kg[(nt + 2) * 1024 + tid + r * 256];
                vf[r] = vg[(nt + 2) * 1024 + tid + r * 256];
            }
        }

        const int KHo = OF_KH + buf * BT * LDK2;
        const int KLo = OF_KL + buf * BT * LDK2;
        const int Vo  = OF_V  + buf * BT * LDV;

        // ---- GEMM1: S[32x64] = (qh+ql)(kh+kl)^T (drop ql*kl); K frags shared ----
        float sacc[2][8][4];
#pragma unroll
        for (int t = 0; t < 2; t++)
#pragma unroll
            for (int ct = 0; ct < 8; ct++)
#pragma unroll
                for (int j = 0; j < 4; j++) sacc[t][ct][j] = 0.f;

#pragma unroll
        for (int ks = 0; ks < 4; ks++) {
            const int ko = ks * 8;
            uint32_t ah[2][4], al[2][4];
#pragma unroll
            for (int t = 0; t < 2; t++) {
                const int oh = qoffh0 + t * 16 * LDQ2 + ko;
                const int ol = qoffl0 + t * 16 * LDQ2 + ko;
                ah[t][0] = sm[oh];
                ah[t][1] = sm[oh + 8 * LDQ2];
                ah[t][2] = sm[oh + 4];
                ah[t][3] = sm[oh + 8 * LDQ2 + 4];
                al[t][0] = sm[ol];
                al[t][1] = sm[ol + 8 * LDQ2];
                al[t][2] = sm[ol + 4];
                al[t][3] = sm[ol + 8 * LDQ2 + 4];
            }
#pragma unroll
            for (int ct = 0; ct < 8; ct++) {
                const int o = (8 * ct + tq) * LDK2 + ko + tc;
                uint32_t bh2[2], bl2[2];
                bh2[0] = sm[KHo + o]; bh2[1] = sm[KHo + o + 4];
                bl2[0] = sm[KLo + o]; bl2[1] = sm[KLo + o + 4];
#pragma unroll
                for (int t = 0; t < 2; t++) {
                    mma16(sacc[t][ct], ah[t], bh2);
                    mma16(sacc[t][ct], ah[t], bl2);
                    mma16(sacc[t][ct], al[t], bh2);
                }
            }
        }

        // ---- epilogue: P = rna_tf32(S^2); denom partials ----
#pragma unroll
        for (int t = 0; t < 2; t++)
#pragma unroll
            for (int ct = 0; ct < 8; ct++) {
                sacc[t][ct][0] = tf32_rna(sacc[t][ct][0] * sacc[t][ct][0]);
                sacc[t][ct][1] = tf32_rna(sacc[t][ct][1] * sacc[t][ct][1]);
                sacc[t][ct][2] = tf32_rna(sacc[t][ct][2] * sacc[t][ct][2]);
                sacc[t][ct][3] = tf32_rna(sacc[t][ct][3] * sacc[t][ct][3]);
                dl[t] += sacc[t][ct][0] + sacc[t][ct][1];
                dh[t] += sacc[t][ct][2] + sacc[t][ct][3];
            }

        // ---- GEMM2 (tf32): O[32x64] += P * V; V frags shared across tiles ----
#pragma unroll
        for (int ks = 0; ks < 8; ks++) {
            uint32_t a[2][4];
#pragma unroll
            for (int t = 0; t < 2; t++) {
                float p0l = __shfl_sync(0xffffffffu, sacc[t][ks][0], slo);
                float p1l = __shfl_sync(0xffffffffu, sacc[t][ks][1], slo);
                float p2l = __shfl_sync(0xffffffffu, sacc[t][ks][2], slo);
                float p3l = __shfl_sync(0xffffffffu, sacc[t][ks][3], slo);
                float p0h = __shfl_sync(0xffffffffu, sacc[t][ks][0], shi);
                float p1h = __shfl_sync(0xffffffffu, sacc[t][ks][1], shi);
                float p2h = __shfl_sync(0xffffffffu, sacc[t][ks][2], shi);
                float p3h = __shfl_sync(0xffffffffu, sacc[t][ks][3], shi);
                a[t][0] = __float_as_uint(odd ? p1l : p0l);
                a[t][1] = __float_as_uint(odd ? p3l : p2l);
                a[t][2] = __float_as_uint(odd ? p1h : p0h);
                a[t][3] = __float_as_uint(odd ? p3h : p2h);
            }
            const int vk = Vo + (8 * ks + tc) * LDV + tq;
#pragma unroll
            for (int ct = 0; ct < 8; ct++) {
                uint32_t vb[2];
                vb[0] = sm[vk + 8 * ct];
                vb[1] = sm[vk + 4 * LDV + 8 * ct];
                mma8(oacc[0][ct], a[0], vb);
                mma8(oacc[1][ct], a[1], vb);
            }
        }
        __syncthreads();
    }

    // ---- denominator reduce over tc lanes; normalize and store ----
    float* og = out + ((size_t)bh * SLEN + (size_t)mt * BM + m0) * DDIM;
#pragma unroll
    for (int t = 0; t < 2; t++) {
        float l = dl[t], h = dh[t];
        l += __shfl_xor_sync(0xffffffffu, l, 1);
        l += __shfl_xor_sync(0xffffffffu, l, 2);
        h += __shfl_xor_sync(0xffffffffu, h, 1);
        h += __shfl_xor_sync(0xffffffffu, h, 2);
        const float il = 1.f / fmaxf(l, EPS_CLAMP);
        const float ih = 1.f / fmaxf(h, EPS_CLAMP);
#pragma unroll
        for (int ct = 0; ct < 8; ct++) {
            int dcol = 8 * ct + 2 * tc;
            *(float2*)(og + (size_t)(t * 16 + tq) * DDIM + dcol) =
                make_float2(oacc[t][ct][0] * il, oacc[t][ct][1] * il);
            *(float2*)(og + (size_t)(t * 16 + tq + 8) * DDIM + dcol) =
                make_float2(oacc[t][ct][2] * ih, oacc[t][ct][3] * ih);
        }
    }
}

extern "C" void kernel_launch(void* const* d_in, const int* in_sizes, int n_in,
                              void* d_out, int out_size) {
    (void)in_sizes; (void)n_in; (void)out_size;
    const float* q = (const float*)d_in[0];
    const float* k = (const float*)d_in[1];
    const float* v = (const float*)d_in[2];
    float* out = (float*)d_out;

    cudaFuncSetAttribute(poly_attn_mma,
                         cudaFuncAttributeMaxDynamicSharedMemorySize, SMEM_BYTES);
    poly_attn_mma<<<dim3(SLEN / BM, 32), 256, SMEM_BYTES>>>(q, k, v, out);
}